// round 16
// baseline (speedup 1.0000x reference)
#include <cuda_runtime.h>
#include <cuda_bf16.h>

#define NTOK 4096
#define DMODEL 256
#define NHEAD 8
#define HEADD 32
#define KDIM 256
#define SCALE 0.17677669529663689f
#define LOG2E 1.4426950408889634f
#define SCALE2 (SCALE * LOG2E)

typedef unsigned long long u64;
typedef unsigned int u32;

// Scratch (device globals — no allocation allowed)
__device__ float g_pe[NHEAD * NTOK];           // [h][n], stores -pe_proj*log2e
__device__ float g_att0[NTOK * DMODEL];        // O partial, keys [0,2048)
__device__ float g_att1[NTOK * DMODEL];        // O partial, keys [2048,4096)
__device__ float g_l[2][NHEAD * NTOK];         // l partials per half
__device__ __nv_bfloat16 g_qb[NTOK * DMODEL];  // Q bf16, PRE-SCALED by SCALE*log2e
__device__ __nv_bfloat16 g_kb[NTOK * DMODEL];  // K bf16 [n][h*32+d]
__device__ __nv_bfloat16 g_vb[NTOK * DMODEL];  // V bf16 [n][h*32+d]

// ---------------- helpers ----------------
__device__ __forceinline__ u32 smem_u32(const void* p) {
  u32 a;
  asm("{ .reg .u64 t; cvta.to.shared.u64 t, %1; cvt.u32.u64 %0, t; }" : "=r"(a) : "l"(p));
  return a;
}
__device__ __forceinline__ float ex2(float x) {
  float y;
  asm("ex2.approx.f32 %0, %1;" : "=f"(y) : "f"(x));
  return y;
}
#define CP_ASYNC16(dst, src)                                                  \
  asm volatile("cp.async.cg.shared.global [%0], [%1], 16;" :: "r"(dst),       \
               "l"(src) : "memory")
#define CP_ASYNC4(dst, src)                                                   \
  asm volatile("cp.async.ca.shared.global [%0], [%1], 4;" :: "r"(dst),        \
               "l"(src) : "memory")
#define CP_COMMIT() asm volatile("cp.async.commit_group;" ::: "memory")
#define CP_WAIT0() asm volatile("cp.async.wait_group 0;" ::: "memory")
#define CP_WAIT1() asm volatile("cp.async.wait_group 1;" ::: "memory")
#define LDSM4(r, addr)                                                        \
  asm volatile("ldmatrix.sync.aligned.m8n8.x4.shared.b16 {%0,%1,%2,%3}, [%4];"\
               : "=r"((r)[0]), "=r"((r)[1]), "=r"((r)[2]), "=r"((r)[3])       \
               : "r"(addr))
#define LDSM4T(r, addr)                                                       \
  asm volatile(                                                               \
      "ldmatrix.sync.aligned.m8n8.x4.trans.shared.b16 {%0,%1,%2,%3}, [%4];"   \
      : "=r"((r)[0]), "=r"((r)[1]), "=r"((r)[2]), "=r"((r)[3])                \
      : "r"(addr))
#define MMA16816(d, a, b0, b1)                                                \
  asm volatile(                                                               \
      "mma.sync.aligned.m16n8k16.row.col.f32.bf16.bf16.f32 "                  \
      "{%0,%1,%2,%3}, {%4,%5,%6,%7}, {%8,%9}, {%0,%1,%2,%3};"                 \
      : "+f"((d)[0]), "+f"((d)[1]), "+f"((d)[2]), "+f"((d)[3])                \
      : "r"((a)[0]), "r"((a)[1]), "r"((a)[2]), "r"((a)[3]), "r"(b0), "r"(b1))
#define MMATF32(d, a, b)                                                      \
  asm volatile(                                                               \
      "mma.sync.aligned.m16n8k8.row.col.f32.tf32.tf32.f32 "                   \
      "{%0,%1,%2,%3}, {%4,%5,%6,%7}, {%8,%9}, {%0,%1,%2,%3};"                 \
      : "+f"((d)[0]), "+f"((d)[1]), "+f"((d)[2]), "+f"((d)[3])                \
      : "r"((a)[0]), "r"((a)[1]), "r"((a)[2]), "r"((a)[3]),                   \
        "r"((b)[0]), "r"((b)[1]))

#define BF16_ONES 0x3F803F80u  // bf16x2 {1.0, 1.0}

// ---------------------------------------------------------------------------
// tf32 GEMM (R15 winner, verbatim): cp.async staging, implicit tf32 trunc,
// tile 64x64, 8 warps, double-buffered commit/wait1 pipeline.
// ---------------------------------------------------------------------------
template <int QKV>
__global__ __launch_bounds__(256) void gemm_tf32_kernel(
    const float* __restrict__ A, const float* __restrict__ B,
    const float* __restrict__ bias, float* __restrict__ C, int Nc) {
  __shared__ __align__(16) u32 As[2][64][20];  // [buf][m][k]
  __shared__ __align__(16) u32 Bs[2][16][68];  // [buf][k][n]
  const int t = threadIdx.x;
  const int w = t >> 5, l = t & 31;
  const int wm = w >> 2, wn = w & 3;
  const int m0 = wm * 32, n0 = wn * 16;
  const int lk = l & 3, lm = l >> 2;
  const int bx = blockIdx.x, by = blockIdx.y;

  const int ar = t >> 2, apc = t & 3;
  const int br = t >> 4, bpc = t & 15;
  const float* Asrc = A + (by * 64 + ar) * KDIM + apc * 4;
  const float* Bsrc = B + br * Nc + bx * 64 + bpc * 4;
  const u32 sA = smem_u32(As), sB = smem_u32(Bs);
  const u32 adst = sA + ar * 80 + apc * 16;
  const u32 bdst = sB + br * 272 + bpc * 16;

  float c[2][2][4];
#pragma unroll
  for (int mt = 0; mt < 2; mt++)
#pragma unroll
    for (int nt = 0; nt < 2; nt++)
#pragma unroll
      for (int i = 0; i < 4; i++) c[mt][nt][i] = 0.f;

  CP_ASYNC16(adst, Asrc);
  CP_ASYNC16(bdst, Bsrc);
  CP_COMMIT();

#pragma unroll
  for (int it = 0; it < 16; ++it) {
    const int buf = it & 1;
    if (it < 15) {
      CP_ASYNC16(adst + (buf ^ 1) * 5120, Asrc + (it + 1) * 16);
      CP_ASYNC16(bdst + (buf ^ 1) * 4352, Bsrc + (it + 1) * 16 * Nc);
      CP_COMMIT();
      CP_WAIT1();
    } else {
      CP_WAIT0();
    }
    __syncthreads();

#pragma unroll
    for (int kc = 0; kc < 2; kc++) {
      const int kq = kc * 8;
      u32 a[2][4], b[2][2];
#pragma unroll
      for (int mt = 0; mt < 2; mt++) {
        a[mt][0] = As[buf][m0 + mt * 16 + lm][kq + lk];
        a[mt][1] = As[buf][m0 + mt * 16 + lm + 8][kq + lk];
        a[mt][2] = As[buf][m0 + mt * 16 + lm][kq + lk + 4];
        a[mt][3] = As[buf][m0 + mt * 16 + lm + 8][kq + lk + 4];
      }
#pragma unroll
      for (int nt = 0; nt < 2; nt++) {
        b[nt][0] = Bs[buf][kq + lk][n0 + nt * 8 + lm];
        b[nt][1] = Bs[buf][kq + lk + 4][n0 + nt * 8 + lm];
      }
#pragma unroll
      for (int mt = 0; mt < 2; mt++)
#pragma unroll
        for (int nt = 0; nt < 2; nt++) MMATF32(c[mt][nt], a[mt], b[nt]);
    }
    __syncthreads();
  }

#pragma unroll
  for (int mt = 0; mt < 2; mt++) {
    const int row = by * 64 + m0 + mt * 16 + lm;
#pragma unroll
    for (int nt = 0; nt < 2; nt++) {
      const int col = bx * 64 + n0 + nt * 8 + 2 * lk;
      const float2 bv2 = *(const float2*)&bias[col];
      float v00 = c[mt][nt][0] + bv2.x, v01 = c[mt][nt][1] + bv2.y;
      float v10 = c[mt][nt][2] + bv2.x, v11 = c[mt][nt][3] + bv2.y;
      if (QKV) {
        const int type = col >> 8, hd = col & 255;
        if (type == 0) {
          v00 *= SCALE2; v01 *= SCALE2; v10 *= SCALE2; v11 *= SCALE2;
        }
        __nv_bfloat16* dst = (type == 0) ? g_qb : (type == 1) ? g_kb : g_vb;
        __nv_bfloat162 p0 = __floats2bfloat162_rn(v00, v01);
        __nv_bfloat162 p1 = __floats2bfloat162_rn(v10, v11);
        *(u32*)(dst + row * DMODEL + hd) = *(u32*)&p0;
        *(u32*)(dst + (row + 8) * DMODEL + hd) = *(u32*)&p1;
      } else {
        *(float2*)&C[row * Nc + col] = make_float2(v00, v01);
        *(float2*)&C[(row + 8) * Nc + col] = make_float2(v10, v11);
      }
    }
  }
}

// ---------------------------------------------------------------------------
// pe_proj: stores -(pe@Wpe + bpe)*log2e so attention can cp.async it raw.
// ---------------------------------------------------------------------------
__global__ __launch_bounds__(256) void pe_proj_kernel(
    const float* __restrict__ pe, const float* __restrict__ Wpe,
    const float* __restrict__ bpe) {
  const int n = blockIdx.x * blockDim.x + threadIdx.x;
  if (n >= NTOK) return;
  float pr[16];
#pragma unroll
  for (int i = 0; i < 4; i++) {
    float4 v = *(const float4*)&pe[n * 16 + i * 4];
    pr[i * 4 + 0] = v.x; pr[i * 4 + 1] = v.y; pr[i * 4 + 2] = v.z; pr[i * 4 + 3] = v.w;
  }
#pragma unroll
  for (int h = 0; h < NHEAD; h++) {
    float s = __ldg(&bpe[h]);
#pragma unroll
    for (int d = 0; d < 16; d++) s += pr[d] * __ldg(&Wpe[d * NHEAD + h]);
    g_pe[h * NTOK + n] = -s * LOG2E;
  }
}

// ---------------------------------------------------------------------------
// Split-K mma.sync flash attention. blockIdx.z = key half (keys z*2048 ..
// z*2048+2047), 16 slabs of 128 keys. Compute core identical to R14/R15
// winner; epilogue writes UNNORMALIZED O to g_att0/g_att1 and partial l to
// g_l[half]. Grid 32x8x2 = 512 blocks -> true 3 blocks/SM residency.
// ---------------------------------------------------------------------------
#define SMB_K(buf) ((buf) ? 0 : 10240)
#define SMB_V(buf) (20480 + (buf) * 10240)
#define SMB_PE(buf) (40960 + (buf) * 512)

__global__ __launch_bounds__(256, 3) void attn_mma_kernel() {
  __shared__ __align__(16) char sm[41984];
  const u32 sb = smem_u32(sm);
  const int t = threadIdx.x;
  const int w = t >> 5, l = t & 31;
  const int h = blockIdx.y;
  const int q0 = blockIdx.x * 128;
  const int half_z = blockIdx.z;
  const int kb0 = half_z * 2048;

  const int u = t & 127, pr_r = u >> 2, pr_p = u & 3;
  const bool isK = t < 128;

  // ---- issue slab 0 (K->buf0, V->buf0, pe->buf0) ----
  if (isK) {
#pragma unroll
    for (int j = 0; j < 4; j++)
      CP_ASYNC16(sb + SMB_K(0) + (pr_r + 32 * j) * 80 + pr_p * 16,
                 g_kb + (kb0 + pr_r + 32 * j) * DMODEL + h * HEADD + pr_p * 8);
    CP_ASYNC4(sb + SMB_PE(0) + t * 4, g_pe + h * NTOK + kb0 + t);
  } else {
#pragma unroll
    for (int j = 0; j < 4; j++)
      CP_ASYNC16(sb + SMB_V(0) + (pr_r + 32 * j) * 80 + pr_p * 16,
                 g_vb + (kb0 + pr_r + 32 * j) * DMODEL + h * HEADD + pr_p * 8);
  }
  CP_COMMIT();

  // ---- stage Q into region [0,10240) ----
#pragma unroll
  for (int c = t; c < 512; c += 256) {
    const int r = c >> 2, p = c & 3;
    uint4 v = *(const uint4*)(g_qb + (q0 + r) * DMODEL + h * HEADD + p * 8);
    *(uint4*)(sm + r * 80 + p * 16) = v;
  }
  __syncthreads();

  // ---- Q fragments (held for whole kernel) ----
  u32 qa[2][4];
  {
    const int qrow = w * 16 + (l & 7) + ((l >> 3) & 1) * 8;
    const int qcol = (l >> 4) * 8;
    u32 qaddr = sb + qrow * 80 + qcol * 2;
    LDSM4(qa[0], qaddr);
    LDSM4(qa[1], qaddr + 32);
  }
  __syncthreads();  // Q region now reusable as K buf1

  float o[4][4];
#pragma unroll
  for (int nd = 0; nd < 4; nd++)
#pragma unroll
    for (int i = 0; i < 4; i++) o[nd][i] = 0.f;
  float ol[4] = {0.f, 0.f, 0.f, 0.f};

  const int kl_row = l & 7;
  const int kl_g = l >> 3;

  for (int it = 0; it < 16; ++it) {
    const int buf = it & 1;
    if (it + 1 < 16) {  // issue next slab into other buffer, keep 1 in flight
      const int base = kb0 + (it + 1) * 128;
      if (isK) {
#pragma unroll
        for (int j = 0; j < 4; j++)
          CP_ASYNC16(sb + SMB_K(buf ^ 1) + (pr_r + 32 * j) * 80 + pr_p * 16,
                     g_kb + (base + pr_r + 32 * j) * DMODEL + h * HEADD + pr_p * 8);
        CP_ASYNC4(sb + SMB_PE(buf ^ 1) + t * 4, g_pe + h * NTOK + base + t);
      } else {
#pragma unroll
        for (int j = 0; j < 4; j++)
          CP_ASYNC16(sb + SMB_V(buf ^ 1) + (pr_r + 32 * j) * 80 + pr_p * 16,
                     g_vb + (base + pr_r + 32 * j) * DMODEL + h * HEADD + pr_p * 8);
      }
      CP_COMMIT();
      CP_WAIT1();
    } else {
      CP_WAIT0();
    }
    __syncthreads();

    const u32 sKb = sb + SMB_K(buf);
    const u32 sVb = sb + SMB_V(buf);
    const float* pev = (const float*)(sm + SMB_PE(buf));

#pragma unroll
    for (int half = 0; half < 2; ++half) {
      const int ro = half * 64;

      // ---- scores (bias in accumulator init) + ex2 -> P fragments ----
      u32 pa[4][4];
#pragma unroll
      for (int n = 0; n < 8; ++n) {
        u32 kb[4];
        LDSM4(kb, sKb + (ro + n * 8 + kl_row) * 80 + kl_g * 16);
        float2 pe2 = *(const float2*)&pev[ro + n * 8 + ((l & 3) << 1)];
        float c[4] = {pe2.x, pe2.y, pe2.x, pe2.y};  // = -pe*log2e
        MMA16816(c, qa[0], kb[0], kb[1]);
        MMA16816(c, qa[1], kb[2], kb[3]);
        float e0 = ex2(c[0]);
        float e1 = ex2(c[1]);
        float e2 = ex2(c[2]);
        float e3 = ex2(c[3]);
        __nv_bfloat162 p01 = __floats2bfloat162_rn(e0, e1);
        __nv_bfloat162 p23 = __floats2bfloat162_rn(e2, e3);
        pa[n >> 1][(n & 1) * 2 + 0] = *(u32*)&p01;
        pa[n >> 1][(n & 1) * 2 + 1] = *(u32*)&p23;
      }

      // ---- l += P @ ones ----
      MMA16816(ol, pa[0], BF16_ONES, BF16_ONES);
      MMA16816(ol, pa[1], BF16_ONES, BF16_ONES);
      MMA16816(ol, pa[2], BF16_ONES, BF16_ONES);
      MMA16816(ol, pa[3], BF16_ONES, BF16_ONES);

      // ---- PV: O[16x32] += P[16x64] @ V[64x32] ----
#pragma unroll
      for (int nd = 0; nd < 4; ++nd) {
        u32 vb0[4], vb1[4];
        LDSM4T(vb0, sVb + (ro + kl_g * 8 + kl_row) * 80 + nd * 16);
        LDSM4T(vb1, sVb + (ro + 32 + kl_g * 8 + kl_row) * 80 + nd * 16);
        MMA16816(o[nd], pa[0], vb0[0], vb0[1]);
        MMA16816(o[nd], pa[1], vb0[2], vb0[3]);
        MMA16816(o[nd], pa[2], vb1[0], vb1[1]);
        MMA16816(o[nd], pa[3], vb1[2], vb1[3]);
      }
    }
    __syncthreads();
  }

  float* oDst = half_z ? g_att1 : g_att0;
  const int row0 = q0 + w * 16 + (l >> 2);
  const int col0 = h * HEADD + ((l & 3) << 1);
#pragma unroll
  for (int nd = 0; nd < 4; ++nd) {
    *(float2*)&oDst[row0 * DMODEL + col0 + nd * 8] =
        make_float2(o[nd][0], o[nd][1]);
    *(float2*)&oDst[(row0 + 8) * DMODEL + col0 + nd * 8] =
        make_float2(o[nd][2], o[nd][3]);
  }
  if ((l & 3) == 0) {  // one lane per row writes partial l
    g_l[half_z][h * NTOK + row0] = ol[0];
    g_l[half_z][h * NTOK + row0 + 8] = ol[2];
  }
}

// ---------------------------------------------------------------------------
// Normalize: g_att0 <- (g_att0 + g_att1) / (l0 + l1). 262144 float4 threads.
// ---------------------------------------------------------------------------
__global__ __launch_bounds__(256) void norm_kernel() {
  const int idx = blockIdx.x * 256 + threadIdx.x;  // one float4 each
  const int n = idx >> 6;
  const int d4 = idx & 63;
  const int h = d4 >> 3;
  const float lsum = g_l[0][h * NTOK + n] + g_l[1][h * NTOK + n];
  const float inv = 1.f / lsum;
  float4 a = *(const float4*)&g_att0[n * DMODEL + d4 * 4];
  float4 b = *(const float4*)&g_att1[n * DMODEL + d4 * 4];
  a.x = (a.x + b.x) * inv;
  a.y = (a.y + b.y) * inv;
  a.z = (a.z + b.z) * inv;
  a.w = (a.w + b.w) * inv;
  *(float4*)&g_att0[n * DMODEL + d4 * 4] = a;
}

// ---------------------------------------------------------------------------
extern "C" void kernel_launch(void* const* d_in, const int* in_sizes, int n_in,
                              void* d_out, int out_size) {
  const float* x    = (const float*)d_in[0];
  const float* pe   = (const float*)d_in[1];
  const float* Wqkv = (const float*)d_in[2];
  const float* bqkv = (const float*)d_in[3];
  const float* Wpe  = (const float*)d_in[4];
  const float* bpe  = (const float*)d_in[5];
  const float* Wout = (const float*)d_in[6];
  const float* bout = (const float*)d_in[7];
  float* out = (float*)d_out;

  void* p_att = nullptr;
  cudaGetSymbolAddress(&p_att, g_att0);

  gemm_tf32_kernel<1><<<dim3(12, 64), 256>>>(x, Wqkv, bqkv, nullptr, 768);
  pe_proj_kernel<<<16, 256>>>(pe, Wpe, bpe);
  attn_mma_kernel<<<dim3(32, 8, 2), 256>>>();
  norm_kernel<<<1024, 256>>>();
  gemm_tf32_kernel<0><<<dim3(4, 64), 256>>>((const float*)p_att, Wout, bout, out, 256);
}